// round 12
// baseline (speedup 1.0000x reference)
#include <cuda_runtime.h>
#include <cuda_fp16.h>
#include <cstdint>

// Problem constants
#define B_SZ    2
#define T_SEQ   2048
#define D_MODEL 1024
#define H_HEADS 16
#define DK      64
#define M_ROWS  (B_SZ * T_SEQ)   // 4096
#define WIN     64
#define MAXD    128

// ---------------------------------------------------------------------------
// Scratch (all fp16 intermediates)
// ---------------------------------------------------------------------------
__device__ __half g_Xh[(size_t)3 * M_ROWS * D_MODEL];    // half(q_in/k_in/v_in)
__device__ __half g_Qh[(size_t)M_ROWS * D_MODEL];
__device__ __half g_Kh[(size_t)M_ROWS * D_MODEL];
__device__ __half g_Vh[(size_t)M_ROWS * D_MODEL];
__device__ __half g_Ah[(size_t)M_ROWS * D_MODEL];
__device__ __half g_WH[(size_t)4 * D_MODEL * D_MODEL];   // half(W[k][n])

__device__ __forceinline__ void mma_f16(float* c, const unsigned* a, const unsigned* b) {
    asm volatile(
        "mma.sync.aligned.m16n8k16.row.col.f32.f16.f16.f32 "
        "{%0,%1,%2,%3}, {%4,%5,%6,%7}, {%8,%9}, {%0,%1,%2,%3};\n"
        : "+f"(c[0]), "+f"(c[1]), "+f"(c[2]), "+f"(c[3])
        : "r"(a[0]), "r"(a[1]), "r"(a[2]), "r"(a[3]), "r"(b[0]), "r"(b[1]));
}

#define LDSM4(R0, R1, R2, R3, ADDR)                                           \
    asm volatile("ldmatrix.sync.aligned.m8n8.x4.shared.b16 {%0,%1,%2,%3}, [%4];" \
                 : "=r"(R0), "=r"(R1), "=r"(R2), "=r"(R3) : "r"(ADDR))
#define LDSM4T(R0, R1, R2, R3, ADDR)                                          \
    asm volatile("ldmatrix.sync.aligned.m8n8.x4.trans.shared.b16 {%0,%1,%2,%3}, [%4];" \
                 : "=r"(R0), "=r"(R1), "=r"(R2), "=r"(R3) : "r"(ADDR))

__device__ __forceinline__ uint32_t smem_u32(const void* p) {
    uint32_t a;
    asm("{ .reg .u64 t; cvta.to.shared.u64 t, %1; cvt.u32.u64 %0, t; }" : "=r"(a) : "l"(p));
    return a;
}

__device__ __forceinline__ void cp16(uint32_t dst, const void* src) {
    asm volatile("cp.async.cg.shared.global [%0], [%1], 16;" :: "r"(dst), "l"(src));
}
__device__ __forceinline__ void cp16z(uint32_t dst, const void* src, bool v) {
    int sz = v ? 16 : 0;
    asm volatile("cp.async.cg.shared.global [%0], [%1], 16, %2;"
                 :: "r"(dst), "l"(src), "r"(sz));
}

// ---------------------------------------------------------------------------
// fp32 -> fp16 streaming converts.
// welem_h: 4 weights.  xconv_h: the 3 activation inputs.
// ---------------------------------------------------------------------------
__global__ __launch_bounds__(256) void welem_h(
    const float* __restrict__ w0, const float* __restrict__ w1,
    const float* __restrict__ w2, const float* __restrict__ w3,
    __half* __restrict__ dst)
{
    const int z = blockIdx.y;
    const float* src = (z == 0) ? w0 : (z == 1) ? w1 : (z == 2) ? w2 : w3;
    __half* d = dst + (size_t)z * D_MODEL * D_MODEL;
    const size_t i4 = (size_t)blockIdx.x * 256 + threadIdx.x;
    float4 v = ((const float4*)src)[i4];
    *(__half2*)(d + i4 * 4)     = __floats2half2_rn(v.x, v.y);
    *(__half2*)(d + i4 * 4 + 2) = __floats2half2_rn(v.z, v.w);
}

__global__ __launch_bounds__(256) void xconv_h(
    const float* __restrict__ x0, const float* __restrict__ x1,
    const float* __restrict__ x2, __half* __restrict__ dst)
{
    const int z = blockIdx.y;
    const float* src = (z == 0) ? x0 : (z == 1) ? x1 : x2;
    __half* d = dst + (size_t)z * M_ROWS * D_MODEL;
    const size_t i4 = (size_t)blockIdx.x * 256 + threadIdx.x;
    float4 v = ((const float4*)src)[i4];
    *(__half2*)(d + i4 * 4)     = __floats2half2_rn(v.x, v.y);
    *(__half2*)(d + i4 * 4 + 2) = __floats2half2_rn(v.z, v.w);
}

// ---------------------------------------------------------------------------
// fp16 mma.sync GEMM. Tile 128x128, BK=64, 3-stage cp.async, 8 warps (2m x 4n),
// m16n8k16, ldmatrix fragments.
// A SMEM: [m][k] stride 72 halves (144B = 9x16B).  B SMEM: [k][n] stride 136
// halves (272B = 17x16B), B frags via ldmatrix.trans.  Both conflict-free.
// CMODE: 0 = C fp32, 1 = C fp16.
// ---------------------------------------------------------------------------
#define GBM 128
#define GBN 128
#define GBK 64
#define HSTR 72
#define BHSTR 136
#define HST_A (GBM * HSTR)      // 9216 halves
#define HST_B (GBK * BHSTR)     // 8704 halves
#define NSTAGE 3
#define GEMM_SMEM (NSTAGE * (HST_A + HST_B) * 2)   // 107520 B

template<int CMODE>
__global__ __launch_bounds__(256, 2) void hgemm_t(
    const __half* __restrict__ A0, const __half* __restrict__ A1, const __half* __restrict__ A2,
    const __half* __restrict__ Wh,
    const float* __restrict__ b0, const float* __restrict__ b1, const float* __restrict__ b2,
    void* __restrict__ C0, void* __restrict__ C1, void* __restrict__ C2)
{
    extern __shared__ __half shh[];
    const uint32_t sb = smem_u32(shh);

    const int z = blockIdx.z;
    const __half* A   = (z == 0) ? A0 : (z == 1) ? A1 : A2;
    const __half* W   = Wh + (size_t)z * D_MODEL * D_MODEL;
    const float* bias = (z == 0) ? b0 : (z == 1) ? b1 : b2;
    void* Cv          = (z == 0) ? C0 : (z == 1) ? C1 : C2;

    const int N = D_MODEL;
    const int tid  = threadIdx.x;
    const int bm   = blockIdx.y * GBM;
    const int bn   = blockIdx.x * GBN;
    const int warp = tid >> 5, lane = tid & 31;
    const int wm = warp & 1;
    const int wn = warp >> 1;
    const int g  = lane >> 2;
    const int tg = lane & 3;
    const int lj = lane >> 3, lr = lane & 7;

    const uint32_t a_base = (uint32_t)((wm * 64 + (lj & 1) * 8 + lr) * HSTR + (lj >> 1) * 8);

    float acc[4][4][4];
#pragma unroll
    for (int mi = 0; mi < 4; mi++)
#pragma unroll
        for (int nj = 0; nj < 4; nj++)
#pragma unroll
            for (int r = 0; r < 4; r++) acc[mi][nj][r] = 0.f;

    auto stage = [&](int p) {
        const int s = p % NSTAGE;
        const uint32_t Asb = sb + (uint32_t)(s * (HST_A + HST_B)) * 2u;
        const uint32_t Bsb = Asb + (uint32_t)HST_A * 2u;
        const int kp = p * GBK;
        // A: 128 rows x 8 chunks = 1024 chunks, 4/thread
#pragma unroll
        for (int i = 0; i < 4; i++) {
            const int idx = tid + i * 256;
            const int row = idx >> 3, c = idx & 7;
            cp16(Asb + (uint32_t)(row * (HSTR * 2) + c * 16),
                 A + (size_t)(bm + row) * D_MODEL + kp + c * 8);
        }
        // B: 64 k-rows x 16 n-chunks = 1024 chunks, 4/thread
#pragma unroll
        for (int i = 0; i < 4; i++) {
            const int idx = tid + i * 256;
            const int row = idx >> 4, c = idx & 15;
            cp16(Bsb + (uint32_t)(row * (BHSTR * 2) + c * 16),
                 W + (size_t)(kp + row) * N + bn + c * 8);
        }
        asm volatile("cp.async.commit_group;" ::: "memory");
    };

    stage(0);
    stage(1);

    const int NPAN = D_MODEL / GBK;   // 16
#pragma unroll 1
    for (int p = 0; p < NPAN; p++) {
        if (p < NPAN - 1)
            asm volatile("cp.async.wait_group 1;" ::: "memory");
        else
            asm volatile("cp.async.wait_group 0;" ::: "memory");
        __syncthreads();

        if (p + 2 < NPAN) stage(p + 2);

        const int s = p % NSTAGE;
        const uint32_t Ab32 = sb + (uint32_t)(s * (HST_A + HST_B)) * 2u;
        const uint32_t Bb32 = Ab32 + (uint32_t)HST_A * 2u;
#pragma unroll
        for (int ks = 0; ks < 4; ks++) {
            unsigned a[4][4], b[4][2];
#pragma unroll
            for (int mi = 0; mi < 4; mi++)
                LDSM4(a[mi][0], a[mi][1], a[mi][2], a[mi][3],
                      Ab32 + (a_base + mi * 16 * HSTR + ks * 16) * 2u);
#pragma unroll
            for (int q = 0; q < 2; q++)
                LDSM4T(b[2 * q][0], b[2 * q][1], b[2 * q + 1][0], b[2 * q + 1][1],
                       Bb32 + ((uint32_t)((ks * 16 + (lj & 1) * 8 + lr) * BHSTR)
                               + wn * 32 + (q * 2 + (lj >> 1)) * 8) * 2u);
#pragma unroll
            for (int mi = 0; mi < 4; mi++)
#pragma unroll
                for (int nj = 0; nj < 4; nj++)
                    mma_f16(acc[mi][nj], a[mi], b[nj]);
        }
    }

    // Epilogue: bias + store
#pragma unroll
    for (int nj = 0; nj < 4; nj++) {
        const int col = bn + wn * 32 + nj * 8 + tg * 2;
        const float2 bv = *(const float2*)&bias[col];
#pragma unroll
        for (int mi = 0; mi < 4; mi++) {
            const int row0 = bm + wm * 64 + mi * 16 + g;
            if (CMODE == 0) {
                float* C = (float*)Cv;
                float2 o0, o1;
                o0.x = acc[mi][nj][0] + bv.x;
                o0.y = acc[mi][nj][1] + bv.y;
                o1.x = acc[mi][nj][2] + bv.x;
                o1.y = acc[mi][nj][3] + bv.y;
                *(float2*)(C + (size_t)row0 * N + col)       = o0;
                *(float2*)(C + (size_t)(row0 + 8) * N + col) = o1;
            } else {
                __half* C = (__half*)Cv;
                *(__half2*)(C + (size_t)row0 * N + col) =
                    __floats2half2_rn(acc[mi][nj][0] + bv.x, acc[mi][nj][1] + bv.y);
                *(__half2*)(C + (size_t)(row0 + 8) * N + col) =
                    __floats2half2_rn(acc[mi][nj][2] + bv.x, acc[mi][nj][3] + bv.y);
            }
        }
    }
}

// ---------------------------------------------------------------------------
// fp16 attention, cp.async staging, half in / half out (unchanged from R11).
// ---------------------------------------------------------------------------
#define HKS 72
#define HPS 72
#define KS_OFF 0
#define VS_OFF (256 * HKS * 2)                  // 36864
#define PS_OFF (2 * VS_OFF)                     // 73728
#define BS_OFF (PS_OFF + 8 * 16 * HPS * 2)      // 92160
#define ATTN_SMEM (BS_OFF + 132 * 4)            // 92688

__global__ __launch_bounds__(256, 2) void attn_h(
    const __half* __restrict__ Q, const __half* __restrict__ Kp,
    const __half* __restrict__ Vp, const float* __restrict__ rel,
    __half* __restrict__ O)
{
    extern __shared__ char smb[];
    float*  bsf = (float*)(smb + BS_OFF);
    const uint32_t sbase = smem_u32(smb);

    const int t0   = blockIdx.x * 128;
    const int h    = blockIdx.y;
    const int b    = blockIdx.z;
    const int base = t0 - WIN;
    const int tid  = threadIdx.x;
    const int warp = tid >> 5, lane = tid & 31;
    const int g = lane >> 2, tg = lane & 3;
    const int lj = lane >> 3, lr = lane & 7;

    const __half* Kg = Kp + (size_t)b * T_SEQ * D_MODEL + h * DK;
    const __half* Vg = Vp + (size_t)b * T_SEQ * D_MODEL + h * DK;

#pragma unroll
    for (int it = 0; it < 16; it++) {
        const int idx = tid + it * 256;
        const int sel = idx >> 11;
        const int r   = idx & 2047;
        const int key = r >> 3, d4 = r & 7;
        const int t   = base + key;
        const uint32_t dst = sbase + (sel ? VS_OFF : KS_OFF)
                           + (uint32_t)(key * HKS + d4 * 8) * 2u;
        const __half* src = (sel ? Vg : Kg) + (size_t)t * D_MODEL + d4 * 8;
        cp16z(dst, src, t >= 0 && t < T_SEQ);
    }
    asm volatile("cp.async.commit_group;" ::: "memory");
    if (tid < 2 * WIN + 1)
        bsf[tid] = rel[(size_t)(tid + MAXD - WIN) * H_HEADS + h];

    const int q0 = t0 + warp * 16;
    const __half* Qg = Q + (size_t)(b * T_SEQ + q0) * D_MODEL + h * DK;
    unsigned qa[4][4];
#pragma unroll
    for (int kt = 0; kt < 4; kt++) {
        const int k0 = kt * 16 + 2 * tg;
        qa[kt][0] = *(const unsigned*)(Qg + (size_t)g       * D_MODEL + k0);
        qa[kt][1] = *(const unsigned*)(Qg + (size_t)(g + 8) * D_MODEL + k0);
        qa[kt][2] = *(const unsigned*)(Qg + (size_t)g       * D_MODEL + k0 + 8);
        qa[kt][3] = *(const unsigned*)(Qg + (size_t)(g + 8) * D_MODEL + k0 + 8);
    }
    asm volatile("cp.async.wait_group 0;" ::: "memory");
    __syncthreads();

    float oacc[8][4];
#pragma unroll
    for (int nt = 0; nt < 8; nt++)
#pragma unroll
        for (int r = 0; r < 4; r++) oacc[nt][r] = 0.f;
    float rs0 = 0.f, rs1 = 0.f;

    const uint32_t Pw32 = sbase + PS_OFF + (uint32_t)(warp * 16 * HPS) * 2u;
    __half* Pw = (__half*)(smb + PS_OFF) + warp * 16 * HPS;

#pragma unroll 1
    for (int c = 0; c < 4; c++) {
        float sacc[8][4];
#pragma unroll
        for (int nt = 0; nt < 8; nt++)
#pragma unroll
            for (int r = 0; r < 4; r++) sacc[nt][r] = 0.f;
#pragma unroll
        for (int kt = 0; kt < 4; kt++) {
            unsigned kb[8][2];
#pragma unroll
            for (int q = 0; q < 4; q++) {
                const uint32_t row = (uint32_t)(c * 64 + (q * 2 + (lj >> 1)) * 8 + lr);
                LDSM4(kb[2 * q][0], kb[2 * q][1], kb[2 * q + 1][0], kb[2 * q + 1][1],
                      sbase + KS_OFF + (row * HKS + kt * 16 + (lj & 1) * 8) * 2u);
            }
#pragma unroll
            for (int nt = 0; nt < 8; nt++)
                mma_f16(sacc[nt], qa[kt], kb[nt]);
        }

        __syncwarp();
#pragma unroll
        for (int nt = 0; nt < 8; nt++) {
            const int col = c * 64 + nt * 8 + 2 * tg;
            const int tk  = base + col;
            const int d0  = tk - (q0 + g);
            const int d2  = tk - (q0 + 8 + g);
            float e0 = 0.f, e1 = 0.f, e2 = 0.f, e3 = 0.f;
            if (tk >= 0 && tk < T_SEQ) {
                if (d0 >= -WIN && d0 <= WIN) e0 = __expf(sacc[nt][0] * 0.125f + bsf[d0 + WIN]);
                if (d2 >= -WIN && d2 <= WIN) e2 = __expf(sacc[nt][2] * 0.125f + bsf[d2 + WIN]);
            }
            if (tk + 1 >= 0 && tk + 1 < T_SEQ) {
                if (d0 + 1 >= -WIN && d0 + 1 <= WIN) e1 = __expf(sacc[nt][1] * 0.125f + bsf[d0 + 1 + WIN]);
                if (d2 + 1 >= -WIN && d2 + 1 <= WIN) e3 = __expf(sacc[nt][3] * 0.125f + bsf[d2 + 1 + WIN]);
            }
            rs0 += e0 + e1;
            rs1 += e2 + e3;
            *(__half2*)&Pw[(size_t)g       * HPS + nt * 8 + 2 * tg] = __floats2half2_rn(e0, e1);
            *(__half2*)&Pw[(size_t)(g + 8) * HPS + nt * 8 + 2 * tg] = __floats2half2_rn(e2, e3);
        }
        __syncwarp();

#pragma unroll
        for (int kt = 0; kt < 4; kt++) {
            unsigned pa[4];
            LDSM4(pa[0], pa[1], pa[2], pa[3],
                  Pw32 + ((uint32_t)(((lj & 1) * 8 + lr) * HPS) + kt * 16 + (lj >> 1) * 8) * 2u);
            unsigned vb[8][2];
#pragma unroll
            for (int q = 0; q < 4; q++) {
                const uint32_t row = (uint32_t)(c * 64 + kt * 16 + (lj & 1) * 8 + lr);
                LDSM4T(vb[2 * q][0], vb[2 * q][1], vb[2 * q + 1][0], vb[2 * q + 1][1],
                       sbase + VS_OFF + (row * HKS + (q * 2 + (lj >> 1)) * 8) * 2u);
            }
#pragma unroll
            for (int nt = 0; nt < 8; nt++)
                mma_f16(oacc[nt], pa, vb[nt]);
        }
    }

    rs0 += __shfl_xor_sync(0xffffffffu, rs0, 1);
    rs0 += __shfl_xor_sync(0xffffffffu, rs0, 2);
    rs1 += __shfl_xor_sync(0xffffffffu, rs1, 1);
    rs1 += __shfl_xor_sync(0xffffffffu, rs1, 2);
    const float i0 = 1.f / rs0, i1 = 1.f / rs1;

    __half* Og = O + (size_t)(b * T_SEQ + q0) * D_MODEL + h * DK;
#pragma unroll
    for (int nt = 0; nt < 8; nt++) {
        *(__half2*)(Og + (size_t)g       * D_MODEL + nt * 8 + 2 * tg) =
            __floats2half2_rn(oacc[nt][0] * i0, oacc[nt][1] * i0);
        *(__half2*)(Og + (size_t)(g + 8) * D_MODEL + nt * 8 + 2 * tg) =
            __floats2half2_rn(oacc[nt][2] * i1, oacc[nt][3] * i1);
    }
}

// ---------------------------------------------------------------------------
// Launch
// ---------------------------------------------------------------------------
extern "C" void kernel_launch(void* const* d_in, const int* in_sizes, int n_in,
                              void* d_out, int out_size)
{
    const float* q_in = (const float*)d_in[0];
    const float* k_in = (const float*)d_in[1];
    const float* v_in = (const float*)d_in[2];
    const float* Wq   = (const float*)d_in[3];
    const float* bq   = (const float*)d_in[4];
    const float* Wk   = (const float*)d_in[5];
    const float* bk   = (const float*)d_in[6];
    const float* Wv   = (const float*)d_in[7];
    const float* bv   = (const float*)d_in[8];
    const float* Wo   = (const float*)d_in[9];
    const float* bo   = (const float*)d_in[10];
    const float* rel  = (const float*)d_in[11];
    float* out = (float*)d_out;

    __half *pX, *pQ, *pK, *pV, *pA, *pWH;
    cudaGetSymbolAddress((void**)&pX, g_Xh);
    cudaGetSymbolAddress((void**)&pQ, g_Qh);
    cudaGetSymbolAddress((void**)&pK, g_Kh);
    cudaGetSymbolAddress((void**)&pV, g_Vh);
    cudaGetSymbolAddress((void**)&pA, g_Ah);
    cudaGetSymbolAddress((void**)&pWH, g_WH);

    cudaFuncSetAttribute(hgemm_t<0>, cudaFuncAttributeMaxDynamicSharedMemorySize,
                         (int)GEMM_SMEM);
    cudaFuncSetAttribute(hgemm_t<1>, cudaFuncAttributeMaxDynamicSharedMemorySize,
                         (int)GEMM_SMEM);
    cudaFuncSetAttribute(attn_h, cudaFuncAttributeMaxDynamicSharedMemorySize,
                         (int)ATTN_SMEM);

    const size_t WSZ = (size_t)D_MODEL * D_MODEL;
    const size_t XSZ = (size_t)M_ROWS * D_MODEL;

    // fp16 conversion prepasses (weights + activation inputs).
    welem_h<<<dim3(D_MODEL * D_MODEL / 4 / 256, 4), 256>>>(Wq, Wk, Wv, Wo, pWH);
    xconv_h<<<dim3(M_ROWS * D_MODEL / 4 / 256, 3), 256>>>(q_in, k_in, v_in, pX);

    // Fused Q/K/V projections: half in, half out.
    dim3 g3(D_MODEL / GBN, M_ROWS / GBM, 3);
    hgemm_t<1><<<g3, 256, GEMM_SMEM>>>(pX, pX + XSZ, pX + 2 * XSZ, pWH,
                                       bq, bk, bv, pQ, pK, pV);

    attn_h<<<dim3(T_SEQ / 128, H_HEADS, B_SZ), 256, ATTN_SMEM>>>(pQ, pK, pV, rel, pA);

    // Output projection: half in, f32 out.
    dim3 g1(D_MODEL / GBN, M_ROWS / GBM, 1);
    hgemm_t<0><<<g1, 256, GEMM_SMEM>>>(pA, pA, pA, pWH + 3 * WSZ,
                                       bo, bo, bo, out, out, out);
}

// round 14
// speedup vs baseline: 1.0047x; 1.0047x over previous
#include <cuda_runtime.h>
#include <cuda_fp16.h>
#include <cstdint>

// Problem constants
#define B_SZ    2
#define T_SEQ   2048
#define D_MODEL 1024
#define H_HEADS 16
#define DK      64
#define M_ROWS  (B_SZ * T_SEQ)   // 4096
#define WIN     64
#define MAXD    128

// ---------------------------------------------------------------------------
// Scratch (all fp16 intermediates)
// ---------------------------------------------------------------------------
__device__ __half g_Xh[(size_t)3 * M_ROWS * D_MODEL];    // half(q_in/k_in/v_in)
__device__ __half g_Qh[(size_t)M_ROWS * D_MODEL];
__device__ __half g_Kh[(size_t)M_ROWS * D_MODEL];
__device__ __half g_Vh[(size_t)M_ROWS * D_MODEL];
__device__ __half g_Ah[(size_t)M_ROWS * D_MODEL];
__device__ __half g_WH[(size_t)4 * D_MODEL * D_MODEL];   // half(W[k][n])

__device__ __forceinline__ void mma_f16(float* c, const unsigned* a, const unsigned* b) {
    asm volatile(
        "mma.sync.aligned.m16n8k16.row.col.f32.f16.f16.f32 "
        "{%0,%1,%2,%3}, {%4,%5,%6,%7}, {%8,%9}, {%0,%1,%2,%3};\n"
        : "+f"(c[0]), "+f"(c[1]), "+f"(c[2]), "+f"(c[3])
        : "r"(a[0]), "r"(a[1]), "r"(a[2]), "r"(a[3]), "r"(b[0]), "r"(b[1]));
}

#define LDSM4(R0, R1, R2, R3, ADDR)                                           \
    asm volatile("ldmatrix.sync.aligned.m8n8.x4.shared.b16 {%0,%1,%2,%3}, [%4];" \
                 : "=r"(R0), "=r"(R1), "=r"(R2), "=r"(R3) : "r"(ADDR))
#define LDSM4T(R0, R1, R2, R3, ADDR)                                          \
    asm volatile("ldmatrix.sync.aligned.m8n8.x4.trans.shared.b16 {%0,%1,%2,%3}, [%4];" \
                 : "=r"(R0), "=r"(R1), "=r"(R2), "=r"(R3) : "r"(ADDR))

__device__ __forceinline__ uint32_t smem_u32(const void* p) {
    uint32_t a;
    asm("{ .reg .u64 t; cvta.to.shared.u64 t, %1; cvt.u32.u64 %0, t; }" : "=r"(a) : "l"(p));
    return a;
}

__device__ __forceinline__ void cp16(uint32_t dst, const void* src) {
    asm volatile("cp.async.cg.shared.global [%0], [%1], 16;" :: "r"(dst), "l"(src));
}
__device__ __forceinline__ void cp16z(uint32_t dst, const void* src, bool v) {
    int sz = v ? 16 : 0;
    asm volatile("cp.async.cg.shared.global [%0], [%1], 16, %2;"
                 :: "r"(dst), "l"(src), "r"(sz));
}

// ---------------------------------------------------------------------------
// Unified fp32 -> fp16 streaming prepass: z = 0..3 weights (1M elem each),
// z = 4..6 activations (4M elem each). grid (4096, 7); weight slices bound-
// check and early-out (only first 1024 blocks do work there).
// ---------------------------------------------------------------------------
__global__ __launch_bounds__(256) void prep_h(
    const float* __restrict__ w0, const float* __restrict__ w1,
    const float* __restrict__ w2, const float* __restrict__ w3,
    const float* __restrict__ x0, const float* __restrict__ x1,
    const float* __restrict__ x2,
    __half* __restrict__ wdst, __half* __restrict__ xdst)
{
    const int z = blockIdx.y;
    const size_t i4 = (size_t)blockIdx.x * 256 + threadIdx.x;
    const float* src;
    __half* d;
    if (z < 4) {
        if (i4 >= (size_t)D_MODEL * D_MODEL / 4) return;
        src = (z == 0) ? w0 : (z == 1) ? w1 : (z == 2) ? w2 : w3;
        d = wdst + (size_t)z * D_MODEL * D_MODEL;
    } else {
        const int y = z - 4;
        src = (y == 0) ? x0 : (y == 1) ? x1 : x2;
        d = xdst + (size_t)y * M_ROWS * D_MODEL;
    }
    float4 v = ((const float4*)src)[i4];
    *(__half2*)(d + i4 * 4)     = __floats2half2_rn(v.x, v.y);
    *(__half2*)(d + i4 * 4 + 2) = __floats2half2_rn(v.z, v.w);
}

// ---------------------------------------------------------------------------
// fp16 mma.sync GEMM. Tile 128x128, BK=64, 3-stage cp.async, 8 warps (2m x 4n),
// m16n8k16, ldmatrix fragments.
// ---------------------------------------------------------------------------
#define GBM 128
#define GBN 128
#define GBK 64
#define HSTR 72
#define BHSTR 136
#define HST_A (GBM * HSTR)      // 9216 halves
#define HST_B (GBK * BHSTR)     // 8704 halves
#define NSTAGE 3
#define GEMM_SMEM (NSTAGE * (HST_A + HST_B) * 2)   // 107520 B

template<int CMODE>
__global__ __launch_bounds__(256, 2) void hgemm_t(
    const __half* __restrict__ A0, const __half* __restrict__ A1, const __half* __restrict__ A2,
    const __half* __restrict__ Wh,
    const float* __restrict__ b0, const float* __restrict__ b1, const float* __restrict__ b2,
    void* __restrict__ C0, void* __restrict__ C1, void* __restrict__ C2)
{
    extern __shared__ __half shh[];
    const uint32_t sb = smem_u32(shh);

    const int z = blockIdx.z;
    const __half* A   = (z == 0) ? A0 : (z == 1) ? A1 : A2;
    const __half* W   = Wh + (size_t)z * D_MODEL * D_MODEL;
    const float* bias = (z == 0) ? b0 : (z == 1) ? b1 : b2;
    void* Cv          = (z == 0) ? C0 : (z == 1) ? C1 : C2;

    const int N = D_MODEL;
    const int tid  = threadIdx.x;
    const int bm   = blockIdx.y * GBM;
    const int bn   = blockIdx.x * GBN;
    const int warp = tid >> 5, lane = tid & 31;
    const int wm = warp & 1;
    const int wn = warp >> 1;
    const int g  = lane >> 2;
    const int tg = lane & 3;
    const int lj = lane >> 3, lr = lane & 7;

    const uint32_t a_base = (uint32_t)((wm * 64 + (lj & 1) * 8 + lr) * HSTR + (lj >> 1) * 8);

    float acc[4][4][4];
#pragma unroll
    for (int mi = 0; mi < 4; mi++)
#pragma unroll
        for (int nj = 0; nj < 4; nj++)
#pragma unroll
            for (int r = 0; r < 4; r++) acc[mi][nj][r] = 0.f;

    auto stage = [&](int p) {
        const int s = p % NSTAGE;
        const uint32_t Asb = sb + (uint32_t)(s * (HST_A + HST_B)) * 2u;
        const uint32_t Bsb = Asb + (uint32_t)HST_A * 2u;
        const int kp = p * GBK;
#pragma unroll
        for (int i = 0; i < 4; i++) {
            const int idx = tid + i * 256;
            const int row = idx >> 3, c = idx & 7;
            cp16(Asb + (uint32_t)(row * (HSTR * 2) + c * 16),
                 A + (size_t)(bm + row) * D_MODEL + kp + c * 8);
        }
#pragma unroll
        for (int i = 0; i < 4; i++) {
            const int idx = tid + i * 256;
            const int row = idx >> 4, c = idx & 15;
            cp16(Bsb + (uint32_t)(row * (BHSTR * 2) + c * 16),
                 W + (size_t)(kp + row) * N + bn + c * 8);
        }
        asm volatile("cp.async.commit_group;" ::: "memory");
    };

    stage(0);
    stage(1);

    const int NPAN = D_MODEL / GBK;   // 16
#pragma unroll 1
    for (int p = 0; p < NPAN; p++) {
        if (p < NPAN - 1)
            asm volatile("cp.async.wait_group 1;" ::: "memory");
        else
            asm volatile("cp.async.wait_group 0;" ::: "memory");
        __syncthreads();

        if (p + 2 < NPAN) stage(p + 2);

        const int s = p % NSTAGE;
        const uint32_t Ab32 = sb + (uint32_t)(s * (HST_A + HST_B)) * 2u;
        const uint32_t Bb32 = Ab32 + (uint32_t)HST_A * 2u;
#pragma unroll
        for (int ks = 0; ks < 4; ks++) {
            unsigned a[4][4], b[4][2];
#pragma unroll
            for (int mi = 0; mi < 4; mi++)
                LDSM4(a[mi][0], a[mi][1], a[mi][2], a[mi][3],
                      Ab32 + (a_base + mi * 16 * HSTR + ks * 16) * 2u);
#pragma unroll
            for (int q = 0; q < 2; q++)
                LDSM4T(b[2 * q][0], b[2 * q][1], b[2 * q + 1][0], b[2 * q + 1][1],
                       Bb32 + ((uint32_t)((ks * 16 + (lj & 1) * 8 + lr) * BHSTR)
                               + wn * 32 + (q * 2 + (lj >> 1)) * 8) * 2u);
#pragma unroll
            for (int mi = 0; mi < 4; mi++)
#pragma unroll
                for (int nj = 0; nj < 4; nj++)
                    mma_f16(acc[mi][nj], a[mi], b[nj]);
        }
    }

    // Epilogue: bias + store
#pragma unroll
    for (int nj = 0; nj < 4; nj++) {
        const int col = bn + wn * 32 + nj * 8 + tg * 2;
        const float2 bv = *(const float2*)&bias[col];
#pragma unroll
        for (int mi = 0; mi < 4; mi++) {
            const int row0 = bm + wm * 64 + mi * 16 + g;
            if (CMODE == 0) {
                float* C = (float*)Cv;
                float2 o0, o1;
                o0.x = acc[mi][nj][0] + bv.x;
                o0.y = acc[mi][nj][1] + bv.y;
                o1.x = acc[mi][nj][2] + bv.x;
                o1.y = acc[mi][nj][3] + bv.y;
                *(float2*)(C + (size_t)row0 * N + col)       = o0;
                *(float2*)(C + (size_t)(row0 + 8) * N + col) = o1;
            } else {
                __half* C = (__half*)Cv;
                *(__half2*)(C + (size_t)row0 * N + col) =
                    __floats2half2_rn(acc[mi][nj][0] + bv.x, acc[mi][nj][1] + bv.y);
                *(__half2*)(C + (size_t)(row0 + 8) * N + col) =
                    __floats2half2_rn(acc[mi][nj][2] + bv.x, acc[mi][nj][3] + bv.y);
            }
        }
    }
}

// ---------------------------------------------------------------------------
// fp16 attention with per-warp chunk skip (verified: warp w needs window keys
// [16w, 16w+143] -> chunks {0,1,2} for w<4, {1,2,3} for w>=4; skipped chunk is
// fully outside the +-64 band, contributing exact zeros -> bit-identical).
// ---------------------------------------------------------------------------
#define HKS 72
#define HPS 72
#define KS_OFF 0
#define VS_OFF (256 * HKS * 2)                  // 36864
#define PS_OFF (2 * VS_OFF)                     // 73728
#define BS_OFF (PS_OFF + 8 * 16 * HPS * 2)      // 92160
#define ATTN_SMEM (BS_OFF + 132 * 4)            // 92688

__global__ __launch_bounds__(256, 2) void attn_h(
    const __half* __restrict__ Q, const __half* __restrict__ Kp,
    const __half* __restrict__ Vp, const float* __restrict__ rel,
    __half* __restrict__ O)
{
    extern __shared__ char smb[];
    float*  bsf = (float*)(smb + BS_OFF);
    const uint32_t sbase = smem_u32(smb);

    const int t0   = blockIdx.x * 128;
    const int h    = blockIdx.y;
    const int b    = blockIdx.z;
    const int base = t0 - WIN;
    const int tid  = threadIdx.x;
    const int warp = tid >> 5, lane = tid & 31;
    const int g = lane >> 2, tg = lane & 3;
    const int lj = lane >> 3, lr = lane & 7;

    const __half* Kg = Kp + (size_t)b * T_SEQ * D_MODEL + h * DK;
    const __half* Vg = Vp + (size_t)b * T_SEQ * D_MODEL + h * DK;

#pragma unroll
    for (int it = 0; it < 16; it++) {
        const int idx = tid + it * 256;
        const int sel = idx >> 11;
        const int r   = idx & 2047;
        const int key = r >> 3, d4 = r & 7;
        const int t   = base + key;
        const uint32_t dst = sbase + (sel ? VS_OFF : KS_OFF)
                           + (uint32_t)(key * HKS + d4 * 8) * 2u;
        const __half* src = (sel ? Vg : Kg) + (size_t)t * D_MODEL + d4 * 8;
        cp16z(dst, src, t >= 0 && t < T_SEQ);
    }
    asm volatile("cp.async.commit_group;" ::: "memory");
    if (tid < 2 * WIN + 1)
        bsf[tid] = rel[(size_t)(tid + MAXD - WIN) * H_HEADS + h];

    const int q0 = t0 + warp * 16;
    const __half* Qg = Q + (size_t)(b * T_SEQ + q0) * D_MODEL + h * DK;
    unsigned qa[4][4];
#pragma unroll
    for (int kt = 0; kt < 4; kt++) {
        const int k0 = kt * 16 + 2 * tg;
        qa[kt][0] = *(const unsigned*)(Qg + (size_t)g       * D_MODEL + k0);
        qa[kt][1] = *(const unsigned*)(Qg + (size_t)(g + 8) * D_MODEL + k0);
        qa[kt][2] = *(const unsigned*)(Qg + (size_t)g       * D_MODEL + k0 + 8);
        qa[kt][3] = *(const unsigned*)(Qg + (size_t)(g + 8) * D_MODEL + k0 + 8);
    }
    asm volatile("cp.async.wait_group 0;" ::: "memory");
    __syncthreads();

    float oacc[8][4];
#pragma unroll
    for (int nt = 0; nt < 8; nt++)
#pragma unroll
        for (int r = 0; r < 4; r++) oacc[nt][r] = 0.f;
    float rs0 = 0.f, rs1 = 0.f;

    const uint32_t Pw32 = sbase + PS_OFF + (uint32_t)(warp * 16 * HPS) * 2u;
    __half* Pw = (__half*)(smb + PS_OFF) + warp * 16 * HPS;

    const int cs = warp >> 2;
#pragma unroll 1
    for (int ci = 0; ci < 3; ci++) {
        const int c = cs + ci;
        // ---- S = Q @ K_chunk^T ----
        float sacc[8][4];
#pragma unroll
        for (int nt = 0; nt < 8; nt++)
#pragma unroll
            for (int r = 0; r < 4; r++) sacc[nt][r] = 0.f;
#pragma unroll
        for (int kt = 0; kt < 4; kt++) {
            unsigned kb[8][2];
#pragma unroll
            for (int q = 0; q < 4; q++) {
                const uint32_t row = (uint32_t)(c * 64 + (q * 2 + (lj >> 1)) * 8 + lr);
                LDSM4(kb[2 * q][0], kb[2 * q][1], kb[2 * q + 1][0], kb[2 * q + 1][1],
                      sbase + KS_OFF + (row * HKS + kt * 16 + (lj & 1) * 8) * 2u);
            }
#pragma unroll
            for (int nt = 0; nt < 8; nt++)
                mma_f16(sacc[nt], qa[kt], kb[nt]);
        }

        // ---- bias + band mask + exp; stage P (half) ----
        __syncwarp();
#pragma unroll
        for (int nt = 0; nt < 8; nt++) {
            const int col = c * 64 + nt * 8 + 2 * tg;
            const int tk  = base + col;
            const int d0  = tk - (q0 + g);
            const int d2  = tk - (q0 + 8 + g);
            float e0 = 0.f, e1 = 0.f, e2 = 0.f, e3 = 0.f;
            if (tk >= 0 && tk < T_SEQ) {
                if (d0 >= -WIN && d0 <= WIN) e0 = __expf(sacc[nt][0] * 0.125f + bsf[d0 + WIN]);
                if (d2 >= -WIN && d2 <= WIN) e2 = __expf(sacc[nt][2] * 0.125f + bsf[d2 + WIN]);
            }
            if (tk + 1 >= 0 && tk + 1 < T_SEQ) {
                if (d0 + 1 >= -WIN && d0 + 1 <= WIN) e1 = __expf(sacc[nt][1] * 0.125f + bsf[d0 + 1 + WIN]);
                if (d2 + 1 >= -WIN && d2 + 1 <= WIN) e3 = __expf(sacc[nt][3] * 0.125f + bsf[d2 + 1 + WIN]);
            }
            rs0 += e0 + e1;
            rs1 += e2 + e3;
            *(__half2*)&Pw[(size_t)g       * HPS + nt * 8 + 2 * tg] = __floats2half2_rn(e0, e1);
            *(__half2*)&Pw[(size_t)(g + 8) * HPS + nt * 8 + 2 * tg] = __floats2half2_rn(e2, e3);
        }
        __syncwarp();

        // ---- O += P_chunk @ V_chunk ----
#pragma unroll
        for (int kt = 0; kt < 4; kt++) {
            unsigned pa[4];
            LDSM4(pa[0], pa[1], pa[2], pa[3],
                  Pw32 + ((uint32_t)(((lj & 1) * 8 + lr) * HPS) + kt * 16 + (lj >> 1) * 8) * 2u);
            unsigned vb[8][2];
#pragma unroll
            for (int q = 0; q < 4; q++) {
                const uint32_t row = (uint32_t)(c * 64 + kt * 16 + (lj & 1) * 8 + lr);
                LDSM4T(vb[2 * q][0], vb[2 * q][1], vb[2 * q + 1][0], vb[2 * q + 1][1],
                       sbase + VS_OFF + (row * HKS + (q * 2 + (lj >> 1)) * 8) * 2u);
            }
#pragma unroll
            for (int nt = 0; nt < 8; nt++)
                mma_f16(oacc[nt], pa, vb[nt]);
        }
    }

    // ---- row sums + normalize + store (half) ----
    rs0 += __shfl_xor_sync(0xffffffffu, rs0, 1);
    rs0 += __shfl_xor_sync(0xffffffffu, rs0, 2);
    rs1 += __shfl_xor_sync(0xffffffffu, rs1, 1);
    rs1 += __shfl_xor_sync(0xffffffffu, rs1, 2);
    const float i0 = 1.f / rs0, i1 = 1.f / rs1;

    __half* Og = O + (size_t)(b * T_SEQ + q0) * D_MODEL + h * DK;
#pragma unroll
    for (int nt = 0; nt < 8; nt++) {
        *(__half2*)(Og + (size_t)g       * D_MODEL + nt * 8 + 2 * tg) =
            __floats2half2_rn(oacc[nt][0] * i0, oacc[nt][1] * i0);
        *(__half2*)(Og + (size_t)(g + 8) * D_MODEL + nt * 8 + 2 * tg) =
            __floats2half2_rn(oacc[nt][2] * i1, oacc[nt][3] * i1);
    }
}

// ---------------------------------------------------------------------------
// Launch
// ---------------------------------------------------------------------------
extern "C" void kernel_launch(void* const* d_in, const int* in_sizes, int n_in,
                              void* d_out, int out_size)
{
    const float* q_in = (const float*)d_in[0];
    const float* k_in = (const float*)d_in[1];
    const float* v_in = (const float*)d_in[2];
    const float* Wq   = (const float*)d_in[3];
    const float* bq   = (const float*)d_in[4];
    const float* Wk   = (const float*)d_in[5];
    const float* bk   = (const float*)d_in[6];
    const float* Wv   = (const float*)d_in[7];
    const float* bv   = (const float*)d_in[8];
    const float* Wo   = (const float*)d_in[9];
    const float* bo   = (const float*)d_in[10];
    const float* rel  = (const float*)d_in[11];
    float* out = (float*)d_out;

    __half *pX, *pQ, *pK, *pV, *pA, *pWH;
    cudaGetSymbolAddress((void**)&pX, g_Xh);
    cudaGetSymbolAddress((void**)&pQ, g_Qh);
    cudaGetSymbolAddress((void**)&pK, g_Kh);
    cudaGetSymbolAddress((void**)&pV, g_Vh);
    cudaGetSymbolAddress((void**)&pA, g_Ah);
    cudaGetSymbolAddress((void**)&pWH, g_WH);

    cudaFuncSetAttribute(hgemm_t<0>, cudaFuncAttributeMaxDynamicSharedMemorySize,
                         (int)GEMM_SMEM);
    cudaFuncSetAttribute(hgemm_t<1>, cudaFuncAttributeMaxDynamicSharedMemorySize,
                         (int)GEMM_SMEM);
    cudaFuncSetAttribute(attn_h, cudaFuncAttributeMaxDynamicSharedMemorySize,
                         (int)ATTN_SMEM);

    const size_t WSZ = (size_t)D_MODEL * D_MODEL;
    const size_t XSZ = (size_t)M_ROWS * D_MODEL;

    // Fused fp16 conversion prepass; grid.x sized for the LARGEST tensor
    // (activations: 4096 blocks), weight slices early-out past 1024.
    prep_h<<<dim3(M_ROWS * D_MODEL / 4 / 256, 7), 256>>>(
        Wq, Wk, Wv, Wo, q_in, k_in, v_in, pWH, pX);

    // Fused Q/K/V projections: half in, half out.
    dim3 g3(D_MODEL / GBN, M_ROWS / GBM, 3);
    hgemm_t<1><<<g3, 256, GEMM_SMEM>>>(pX, pX + XSZ, pX + 2 * XSZ, pWH,
                                       bq, bk, bv, pQ, pK, pV);

    attn_h<<<dim3(T_SEQ / 128, H_HEADS, B_SZ), 256, ATTN_SMEM>>>(pQ, pK, pV, rel, pA);

    // Output projection: half in, f32 out.
    dim3 g1(D_MODEL / GBN, M_ROWS / GBM, 1);
    hgemm_t<0><<<g1, 256, GEMM_SMEM>>>(pA, pA, pA, pWH + 3 * WSZ,
                                       bo, bo, bo, out, out, out);
}

// round 16
// speedup vs baseline: 1.0604x; 1.0554x over previous
#include <cuda_runtime.h>
#include <cuda_fp16.h>
#include <cstdint>

// Problem constants
#define B_SZ    2
#define T_SEQ   2048
#define D_MODEL 1024
#define H_HEADS 16
#define DK      64
#define M_ROWS  (B_SZ * T_SEQ)   // 4096
#define WIN     64
#define MAXD    128

// ---------------------------------------------------------------------------
// Scratch (fp16 intermediates)
// ---------------------------------------------------------------------------
__device__ __half g_Qh[(size_t)M_ROWS * D_MODEL];
__device__ __half g_Kh[(size_t)M_ROWS * D_MODEL];
__device__ __half g_Vh[(size_t)M_ROWS * D_MODEL];
__device__ __half g_Ah[(size_t)M_ROWS * D_MODEL];
__device__ __half g_WH[(size_t)4 * D_MODEL * D_MODEL];   // half(W[k][n])

__device__ __forceinline__ void mma_f16(float* c, const unsigned* a, const unsigned* b) {
    asm volatile(
        "mma.sync.aligned.m16n8k16.row.col.f32.f16.f16.f32 "
        "{%0,%1,%2,%3}, {%4,%5,%6,%7}, {%8,%9}, {%0,%1,%2,%3};\n"
        : "+f"(c[0]), "+f"(c[1]), "+f"(c[2]), "+f"(c[3])
        : "r"(a[0]), "r"(a[1]), "r"(a[2]), "r"(a[3]), "r"(b[0]), "r"(b[1]));
}

#define LDSM4(R0, R1, R2, R3, ADDR)                                           \
    asm volatile("ldmatrix.sync.aligned.m8n8.x4.shared.b16 {%0,%1,%2,%3}, [%4];" \
                 : "=r"(R0), "=r"(R1), "=r"(R2), "=r"(R3) : "r"(ADDR))
#define LDSM4T(R0, R1, R2, R3, ADDR)                                          \
    asm volatile("ldmatrix.sync.aligned.m8n8.x4.trans.shared.b16 {%0,%1,%2,%3}, [%4];" \
                 : "=r"(R0), "=r"(R1), "=r"(R2), "=r"(R3) : "r"(ADDR))

__device__ __forceinline__ uint32_t smem_u32(const void* p) {
    uint32_t a;
    asm("{ .reg .u64 t; cvta.to.shared.u64 t, %1; cvt.u32.u64 %0, t; }" : "=r"(a) : "l"(p));
    return a;
}

__device__ __forceinline__ void cp16(uint32_t dst, const void* src) {
    asm volatile("cp.async.cg.shared.global [%0], [%1], 16;" :: "r"(dst), "l"(src));
}
__device__ __forceinline__ void cp16z(uint32_t dst, const void* src, bool v) {
    int sz = v ? 16 : 0;
    asm volatile("cp.async.cg.shared.global [%0], [%1], 16, %2;"
                 :: "r"(dst), "l"(src), "r"(sz));
}

// ---------------------------------------------------------------------------
// Weight-only fp16 prepass: WH[z][k][n] = half(W[k][n]). grid (1024, 4).
// ---------------------------------------------------------------------------
__global__ __launch_bounds__(256) void welem_h(
    const float* __restrict__ w0, const float* __restrict__ w1,
    const float* __restrict__ w2, const float* __restrict__ w3,
    __half* __restrict__ dst)
{
    const int z = blockIdx.y;
    const float* src = (z == 0) ? w0 : (z == 1) ? w1 : (z == 2) ? w2 : w3;
    __half* d = dst + (size_t)z * D_MODEL * D_MODEL;
    const size_t i4 = (size_t)blockIdx.x * 256 + threadIdx.x;
    float4 v = ((const float4*)src)[i4];
    *(__half2*)(d + i4 * 4)     = __floats2half2_rn(v.x, v.y);
    *(__half2*)(d + i4 * 4 + 2) = __floats2half2_rn(v.z, v.w);
}

// ---------------------------------------------------------------------------
// GEMM #1 (QKV): f32 A in (inline cvt during staging), half C out.
// Tile 128x128, BK=32, 3-stage cp.async (B) + register-prefetch (A).
// A SMEM stride 40 halves; B SMEM [k][n] stride 136 halves, ldmatrix.trans.
// (R11-proven kernel.)
// ---------------------------------------------------------------------------
#define GBM 128
#define GBN 128
#define G32_BK 32
#define G32_HSTR 40
#define G32_BHSTR 136
#define G32_A (GBM * G32_HSTR)        // 5120 halves
#define G32_B (G32_BK * G32_BHSTR)    // 4352 halves
#define G32_NS 3
#define G32_SMEM (G32_NS * (G32_A + G32_B) * 2)   // 56832 B

__global__ __launch_bounds__(256, 2) void hgemm_qkv(
    const float* __restrict__ A0, const float* __restrict__ A1, const float* __restrict__ A2,
    const __half* __restrict__ Wh,
    const float* __restrict__ b0, const float* __restrict__ b1, const float* __restrict__ b2,
    __half* __restrict__ C0, __half* __restrict__ C1, __half* __restrict__ C2)
{
    extern __shared__ __half shh[];
    const uint32_t sb = smem_u32(shh);

    const int z = blockIdx.z;
    const float* A    = (z == 0) ? A0 : (z == 1) ? A1 : A2;
    const __half* W   = Wh + (size_t)z * D_MODEL * D_MODEL;
    const float* bias = (z == 0) ? b0 : (z == 1) ? b1 : b2;
    __half* C         = (z == 0) ? C0 : (z == 1) ? C1 : C2;

    const int N = D_MODEL;
    const int tid  = threadIdx.x;
    const int bm   = blockIdx.y * GBM;
    const int bn   = blockIdx.x * GBN;
    const int warp = tid >> 5, lane = tid & 31;
    const int wm = warp & 1;
    const int wn = warp >> 1;
    const int g  = lane >> 2;
    const int tg = lane & 3;
    const int lj = lane >> 3, lr = lane & 7;

    const int am0 = tid >> 3, akq = tid & 7;
    const uint32_t a_base = (uint32_t)((wm * 64 + (lj & 1) * 8 + lr) * G32_HSTR + (lj >> 1) * 8);

    float acc[4][4][4];
#pragma unroll
    for (int mi = 0; mi < 4; mi++)
#pragma unroll
        for (int nj = 0; nj < 4; nj++)
#pragma unroll
            for (int r = 0; r < 4; r++) acc[mi][nj][r] = 0.f;

    auto stageB = [&](int p) {
        const int s = p % G32_NS;
        const uint32_t Bsb = sb + (uint32_t)(s * (G32_A + G32_B) + G32_A) * 2u;
        const int kp = p * G32_BK;
#pragma unroll
        for (int i = 0; i < 2; i++) {
            const int idx = tid + i * 256;
            const int row = idx >> 4, c = idx & 15;
            cp16(Bsb + (uint32_t)(row * (G32_BHSTR * 2) + c * 16),
                 W + (size_t)(kp + row) * N + bn + c * 8);
        }
        asm volatile("cp.async.commit_group;" ::: "memory");
    };
    auto ldA = [&](int p, float4* ar) {
        const int kp = p * G32_BK;
#pragma unroll
        for (int i = 0; i < 4; i++)
            ar[i] = *(const float4*)(A + (size_t)(bm + am0 + 32 * i) * D_MODEL + kp + akq * 4);
    };
    auto stA = [&](int p, const float4* ar) {
        const int s = p % G32_NS;
        __half* As = shh + s * (G32_A + G32_B);
#pragma unroll
        for (int i = 0; i < 4; i++) {
            *(__half2*)&As[(am0 + 32 * i) * G32_HSTR + akq * 4]     = __floats2half2_rn(ar[i].x, ar[i].y);
            *(__half2*)&As[(am0 + 32 * i) * G32_HSTR + akq * 4 + 2] = __floats2half2_rn(ar[i].z, ar[i].w);
        }
    };

    stageB(0);
    stageB(1);
    {
        float4 t[4];
        ldA(0, t); stA(0, t);
        ldA(1, t); stA(1, t);
    }

    const int NPAN = D_MODEL / G32_BK;   // 32
#pragma unroll 1
    for (int p = 0; p < NPAN; p++) {
        if (p < NPAN - 1)
            asm volatile("cp.async.wait_group 1;" ::: "memory");
        else
            asm volatile("cp.async.wait_group 0;" ::: "memory");
        __syncthreads();

        float4 ar[4];
        const bool pre = (p + 2 < NPAN);
        if (pre) {
            ldA(p + 2, ar);
            stageB(p + 2);
        }

        const int s = p % G32_NS;
        const uint32_t Ab32 = sb + (uint32_t)(s * (G32_A + G32_B)) * 2u;
        const uint32_t Bb32 = Ab32 + (uint32_t)G32_A * 2u;
#pragma unroll
        for (int ks = 0; ks < 2; ks++) {
            unsigned a[4][4], b[4][2];
#pragma unroll
            for (int mi = 0; mi < 4; mi++)
                LDSM4(a[mi][0], a[mi][1], a[mi][2], a[mi][3],
                      Ab32 + (a_base + mi * 16 * G32_HSTR + ks * 16) * 2u);
#pragma unroll
            for (int q = 0; q < 2; q++)
                LDSM4T(b[2 * q][0], b[2 * q][1], b[2 * q + 1][0], b[2 * q + 1][1],
                       Bb32 + ((uint32_t)((ks * 16 + (lj & 1) * 8 + lr) * G32_BHSTR)
                               + wn * 32 + (q * 2 + (lj >> 1)) * 8) * 2u);
#pragma unroll
            for (int mi = 0; mi < 4; mi++)
#pragma unroll
                for (int nj = 0; nj < 4; nj++)
                    mma_f16(acc[mi][nj], a[mi], b[nj]);
        }

        if (pre) stA(p + 2, ar);
    }

    // Epilogue: bias + store (half)
#pragma unroll
    for (int nj = 0; nj < 4; nj++) {
        const int col = bn + wn * 32 + nj * 8 + tg * 2;
        const float2 bv = *(const float2*)&bias[col];
#pragma unroll
        for (int mi = 0; mi < 4; mi++) {
            const int row0 = bm + wm * 64 + mi * 16 + g;
            *(__half2*)(C + (size_t)row0 * N + col) =
                __floats2half2_rn(acc[mi][nj][0] + bv.x, acc[mi][nj][1] + bv.y);
            *(__half2*)(C + (size_t)(row0 + 8) * N + col) =
                __floats2half2_rn(acc[mi][nj][2] + bv.x, acc[mi][nj][3] + bv.y);
        }
    }
}

// ---------------------------------------------------------------------------
// GEMM #2 (out-proj): half A in (pure cp.async), f32 C out.
// Tile 128x128, BK=64, 3-stage. (R14-proven kernel, 36.4us.)
// ---------------------------------------------------------------------------
#define G64_BK 64
#define G64_HSTR 72
#define G64_BHSTR 136
#define G64_A (GBM * G64_HSTR)        // 9216 halves
#define G64_B (G64_BK * G64_BHSTR)    // 8704 halves
#define G64_NS 3
#define G64_SMEM (G64_NS * (G64_A + G64_B) * 2)   // 107520 B

__global__ __launch_bounds__(256, 2) void hgemm_out(
    const __half* __restrict__ A, const __half* __restrict__ W,
    const float* __restrict__ bias, float* __restrict__ C)
{
    extern __shared__ __half shh[];
    const uint32_t sb = smem_u32(shh);

    const int N = D_MODEL;
    const int tid  = threadIdx.x;
    const int bm   = blockIdx.y * GBM;
    const int bn   = blockIdx.x * GBN;
    const int warp = tid >> 5, lane = tid & 31;
    const int wm = warp & 1;
    const int wn = warp >> 1;
    const int g  = lane >> 2;
    const int tg = lane & 3;
    const int lj = lane >> 3, lr = lane & 7;

    const uint32_t a_base = (uint32_t)((wm * 64 + (lj & 1) * 8 + lr) * G64_HSTR + (lj >> 1) * 8);

    float acc[4][4][4];
#pragma unroll
    for (int mi = 0; mi < 4; mi++)
#pragma unroll
        for (int nj = 0; nj < 4; nj++)
#pragma unroll
            for (int r = 0; r < 4; r++) acc[mi][nj][r] = 0.f;

    auto stage = [&](int p) {
        const int s = p % G64_NS;
        const uint32_t Asb = sb + (uint32_t)(s * (G64_A + G64_B)) * 2u;
        const uint32_t Bsb = Asb + (uint32_t)G64_A * 2u;
        const int kp = p * G64_BK;
#pragma unroll
        for (int i = 0; i < 4; i++) {
            const int idx = tid + i * 256;
            const int row = idx >> 3, c = idx & 7;
            cp16(Asb + (uint32_t)(row * (G64_HSTR * 2) + c * 16),
                 A + (size_t)(bm + row) * D_MODEL + kp + c * 8);
        }
#pragma unroll
        for (int i = 0; i < 4; i++) {
            const int idx = tid + i * 256;
            const int row = idx >> 4, c = idx & 15;
            cp16(Bsb + (uint32_t)(row * (G64_BHSTR * 2) + c * 16),
                 W + (size_t)(kp + row) * N + bn + c * 8);
        }
        asm volatile("cp.async.commit_group;" ::: "memory");
    };

    stage(0);
    stage(1);

    const int NPAN = D_MODEL / G64_BK;   // 16
#pragma unroll 1
    for (int p = 0; p < NPAN; p++) {
        if (p < NPAN - 1)
            asm volatile("cp.async.wait_group 1;" ::: "memory");
        else
            asm volatile("cp.async.wait_group 0;" ::: "memory");
        __syncthreads();

        if (p + 2 < NPAN) stage(p + 2);

        const int s = p % G64_NS;
        const uint32_t Ab32 = sb + (uint32_t)(s * (G64_A + G64_B)) * 2u;
        const uint32_t Bb32 = Ab32 + (uint32_t)G64_A * 2u;
#pragma unroll
        for (int ks = 0; ks < 4; ks++) {
            unsigned a[4][4], b[4][2];
#pragma unroll
            for (int mi = 0; mi < 4; mi++)
                LDSM4(a[mi][0], a[mi][1], a[mi][2], a[mi][3],
                      Ab32 + (a_base + mi * 16 * G64_HSTR + ks * 16) * 2u);
#pragma unroll
            for (int q = 0; q < 2; q++)
                LDSM4T(b[2 * q][0], b[2 * q][1], b[2 * q + 1][0], b[2 * q + 1][1],
                       Bb32 + ((uint32_t)((ks * 16 + (lj & 1) * 8 + lr) * G64_BHSTR)
                               + wn * 32 + (q * 2 + (lj >> 1)) * 8) * 2u);
#pragma unroll
            for (int mi = 0; mi < 4; mi++)
#pragma unroll
                for (int nj = 0; nj < 4; nj++)
                    mma_f16(acc[mi][nj], a[mi], b[nj]);
        }
    }

    // Epilogue: bias + store (f32)
#pragma unroll
    for (int nj = 0; nj < 4; nj++) {
        const int col = bn + wn * 32 + nj * 8 + tg * 2;
        const float2 bv = *(const float2*)&bias[col];
#pragma unroll
        for (int mi = 0; mi < 4; mi++) {
            const int row0 = bm + wm * 64 + mi * 16 + g;
            float2 o0, o1;
            o0.x = acc[mi][nj][0] + bv.x;
            o0.y = acc[mi][nj][1] + bv.y;
            o1.x = acc[mi][nj][2] + bv.x;
            o1.y = acc[mi][nj][3] + bv.y;
            *(float2*)(C + (size_t)row0 * N + col)       = o0;
            *(float2*)(C + (size_t)(row0 + 8) * N + col) = o1;
        }
    }
}

// ---------------------------------------------------------------------------
// fp16 attention with per-warp chunk skip (R14-proven: warp w needs window
// keys [16w, 16w+143] -> chunks {0,1,2} for w<4, {1,2,3} for w>=4; skipped
// chunk is fully masked -> bit-identical output, 25% less work).
// ---------------------------------------------------------------------------
#define HKS 72
#define HPS 72
#define KS_OFF 0
#define VS_OFF (256 * HKS * 2)                  // 36864
#define PS_OFF (2 * VS_OFF)                     // 73728
#define BS_OFF (PS_OFF + 8 * 16 * HPS * 2)      // 92160
#define ATTN_SMEM (BS_OFF + 132 * 4)            // 92688

__global__ __launch_bounds__(256, 2) void attn_h(
    const __half* __restrict__ Q, const __half* __restrict__ Kp,
    const __half* __restrict__ Vp, const float* __restrict__ rel,
    __half* __restrict__ O)
{
    extern __shared__ char smb[];
    float*  bsf = (float*)(smb + BS_OFF);
    const uint32_t sbase = smem_u32(smb);

    const int t0   = blockIdx.x * 128;
    const int h    = blockIdx.y;
    const int b    = blockIdx.z;
    const int base = t0 - WIN;
    const int tid  = threadIdx.x;
    const int warp = tid >> 5, lane = tid & 31;
    const int g = lane >> 2, tg = lane & 3;
    const int lj = lane >> 3, lr = lane & 7;

    const __half* Kg = Kp + (size_t)b * T_SEQ * D_MODEL + h * DK;
    const __half* Vg = Vp + (size_t)b * T_SEQ * D_MODEL + h * DK;

#pragma unroll
    for (int it = 0; it < 16; it++) {
        const int idx = tid + it * 256;
        const int sel = idx >> 11;
        const int r   = idx & 2047;
        const int key = r >> 3, d4 = r & 7;
        const int t   = base + key;
        const uint32_t dst = sbase + (sel ? VS_OFF : KS_OFF)
                           + (uint32_t)(key * HKS + d4 * 8) * 2u;
        const __half* src = (sel ? Vg : Kg) + (size_t)t * D_MODEL + d4 * 8;
        cp16z(dst, src, t >= 0 && t < T_SEQ);
    }
    asm volatile("cp.async.commit_group;" ::: "memory");
    if (tid < 2 * WIN + 1)
        bsf[tid] = rel[(size_t)(tid + MAXD - WIN) * H_HEADS + h];

    const int q0 = t0 + warp * 16;
    const __half* Qg = Q + (size_t)(b * T_SEQ + q0) * D_MODEL + h * DK;
    unsigned qa[4][4];
#pragma unroll
    for (int kt = 0; kt < 4; kt++) {
        const int k0 = kt * 16 + 2 * tg;
        qa[kt][0] = *(const unsigned*)(Qg + (size_t)g       * D_MODEL + k0);
        qa[kt][1] = *(const unsigned*)(Qg + (size_t)(g + 8) * D_MODEL + k0);
        qa[kt][2] = *(const unsigned*)(Qg + (size_t)g       * D_MODEL + k0 + 8);
        qa[kt][3] = *(const unsigned*)(Qg + (size_t)(g + 8) * D_MODEL + k0 + 8);
    }
    asm volatile("cp.async.wait_group 0;" ::: "memory");
    __syncthreads();

    float oacc[8][4];
#pragma unroll
    for (int nt = 0; nt < 8; nt++)
#pragma unroll
        for (int r = 0; r < 4; r++) oacc[nt][r] = 0.f;
    float rs0 = 0.f, rs1 = 0.f;

    const uint32_t Pw32 = sbase + PS_OFF + (uint32_t)(warp * 16 * HPS) * 2u;
    __half* Pw = (__half*)(smb + PS_OFF) + warp * 16 * HPS;

    const int cs = warp >> 2;
#pragma unroll 1
    for (int ci = 0; ci < 3; ci++) {
        const int c = cs + ci;
        float sacc[8][4];
#pragma unroll
        for (int nt = 0; nt < 8; nt++)
#pragma unroll
            for (int r = 0; r < 4; r++) sacc[nt][r] = 0.f;
#pragma unroll
        for (int kt = 0; kt < 4; kt++) {
            unsigned kb[8][2];
#pragma unroll
            for (int q = 0; q < 4; q++) {
                const uint32_t row = (uint32_t)(c * 64 + (q * 2 + (lj >> 1)) * 8 + lr);
                LDSM4(kb[2 * q][0], kb[2 * q][1], kb[2 * q + 1][0], kb[2 * q + 1][1],
                      sbase + KS_OFF + (row * HKS + kt * 16 + (lj & 1) * 8) * 2u);
            }
#pragma unroll
            for (int nt = 0; nt < 8; nt++)
                mma_f16(sacc[nt], qa[kt], kb[nt]);
        }

        __syncwarp();
#pragma unroll
        for (int nt = 0; nt < 8; nt++) {
            const int col = c * 64 + nt * 8 + 2 * tg;
            const int tk  = base + col;
            const int d0  = tk - (q0 + g);
            const int d2  = tk - (q0 + 8 + g);
            float e0 = 0.f, e1 = 0.f, e2 = 0.f, e3 = 0.f;
            if (tk >= 0 && tk < T_SEQ) {
                if (d0 >= -WIN && d0 <= WIN) e0 = __expf(sacc[nt][0] * 0.125f + bsf[d0 + WIN]);
                if (d2 >= -WIN && d2 <= WIN) e2 = __expf(sacc[nt][2] * 0.125f + bsf[d2 + WIN]);
            }
            if (tk + 1 >= 0 && tk + 1 < T_SEQ) {
                if (d0 + 1 >= -WIN && d0 + 1 <= WIN) e1 = __expf(sacc[nt][1] * 0.125f + bsf[d0 + 1 + WIN]);
                if (d2 + 1 >= -WIN && d2 + 1 <= WIN) e3 = __expf(sacc[nt][3] * 0.125f + bsf[d2 + 1 + WIN]);
            }
            rs0 += e0 + e1;
            rs1 += e2 + e3;
            *(__half2*)&Pw[(size_t)g       * HPS + nt * 8 + 2 * tg] = __floats2half2_rn(e0, e1);
            *(__half2*)&Pw[(size_t)(g + 8) * HPS + nt * 8 + 2 * tg] = __floats2half2_rn(e2, e3);
        }
        __syncwarp();

#pragma unroll
        for (int kt = 0; kt < 4; kt++) {
            unsigned pa[4];
            LDSM4(pa[0], pa[1], pa[2], pa[3],
                  Pw32 + ((uint32_t)(((lj & 1) * 8 + lr) * HPS) + kt * 16 + (lj >> 1) * 8) * 2u);
            unsigned vb[8][2];
#pragma unroll
            for (int q = 0; q < 4; q++) {
                const uint32_t row = (uint32_t)(c * 64 + kt * 16 + (lj & 1) * 8 + lr);
                LDSM4T(vb[2 * q][0], vb[2 * q][1], vb[2 * q + 1][0], vb[2 * q + 1][1],
                       sbase + VS_OFF + (row * HKS + (q * 2 + (lj >> 1)) * 8) * 2u);
            }
#pragma unroll
            for (int nt = 0; nt < 8; nt++)
                mma_f16(oacc[nt], pa, vb[nt]);
        }
    }

    rs0 += __shfl_xor_sync(0xffffffffu, rs0, 1);
    rs0 += __shfl_xor_sync(0xffffffffu, rs0, 2);
    rs1 += __shfl_xor_sync(0xffffffffu, rs1, 1);
    rs1 += __shfl_xor_sync(0xffffffffu, rs1, 2);
    const float i0 = 1.f / rs0, i1 = 1.f / rs1;

    __half* Og = O + (size_t)(b * T_SEQ + q0) * D_MODEL + h * DK;
#pragma unroll
    for (int nt = 0; nt < 8; nt++) {
        *(__half2*)(Og + (size_t)g       * D_MODEL + nt * 8 + 2 * tg) =
            __floats2half2_rn(oacc[nt][0] * i0, oacc[nt][1] * i0);
        *(__half2*)(Og + (size_t)(g + 8) * D_MODEL + nt * 8 + 2 * tg) =
            __floats2half2_rn(oacc[nt][2] * i1, oacc[nt][3] * i1);
    }
}

// ---------------------------------------------------------------------------
// Launch
// ---------------------------------------------------------------------------
extern "C" void kernel_launch(void* const* d_in, const int* in_sizes, int n_in,
                              void* d_out, int out_size)
{
    const float* q_in = (const float*)d_in[0];
    const float* k_in = (const float*)d_in[1];
    const float* v_in = (const float*)d_in[2];
    const float* Wq   = (const float*)d_in[3];
    const float* bq   = (const float*)d_in[4];
    const float* Wk   = (const float*)d_in[5];
    const float* bk   = (const float*)d_in[6];
    const float* Wv   = (const float*)d_in[7];
    const float* bv   = (const float*)d_in[8];
    const float* Wo   = (const float*)d_in[9];
    const float* bo   = (const float*)d_in[10];
    const float* rel  = (const float*)d_in[11];
    float* out = (float*)d_out;

    __half *pQ, *pK, *pV, *pA, *pWH;
    cudaGetSymbolAddress((void**)&pQ, g_Qh);
    cudaGetSymbolAddress((void**)&pK, g_Kh);
    cudaGetSymbolAddress((void**)&pV, g_Vh);
    cudaGetSymbolAddress((void**)&pA, g_Ah);
    cudaGetSymbolAddress((void**)&pWH, g_WH);

    cudaFuncSetAttribute(hgemm_qkv, cudaFuncAttributeMaxDynamicSharedMemorySize,
                         (int)G32_SMEM);
    cudaFuncSetAttribute(hgemm_out, cudaFuncAttributeMaxDynamicSharedMemorySize,
                         (int)G64_SMEM);
    cudaFuncSetAttribute(attn_h, cudaFuncAttributeMaxDynamicSharedMemorySize,
                         (int)ATTN_SMEM);

    const size_t WSZ = (size_t)D_MODEL * D_MODEL;

    // Weight-only fp16 prepass (~4us).
    welem_h<<<dim3(D_MODEL * D_MODEL / 4 / 256, 4), 256>>>(Wq, Wk, Wv, Wo, pWH);

    // Fused Q/K/V projections: f32 in (inline cvt), half out.
    dim3 g3(D_MODEL / GBN, M_ROWS / GBM, 3);
    hgemm_qkv<<<g3, 256, G32_SMEM>>>(q_in, k_in, v_in, pWH,
                                     bq, bk, bv, pQ, pK, pV);

    attn_h<<<dim3(T_SEQ / 128, H_HEADS, B_SZ), 256, ATTN_SMEM>>>(pQ, pK, pV, rel, pA);

    // Output projection: half in, f32 out, BK=64.
    dim3 g1(D_MODEL / GBN, M_ROWS / GBM, 1);
    hgemm_out<<<g1, 256, G64_SMEM>>>(pA, pWH + 3 * WSZ, bo, out);
}

// round 17
// speedup vs baseline: 1.0683x; 1.0075x over previous
#include <cuda_runtime.h>
#include <cuda_fp16.h>
#include <cstdint>

// Problem constants
#define B_SZ    2
#define T_SEQ   2048
#define D_MODEL 1024
#define H_HEADS 16
#define DK      64
#define M_ROWS  (B_SZ * T_SEQ)   // 4096
#define WIN     64
#define MAXD    128

// ---------------------------------------------------------------------------
// Scratch (fp16 intermediates)
// ---------------------------------------------------------------------------
__device__ __half g_Qh[(size_t)M_ROWS * D_MODEL];
__device__ __half g_Kh[(size_t)M_ROWS * D_MODEL];
__device__ __half g_Vh[(size_t)M_ROWS * D_MODEL];
__device__ __half g_Ah[(size_t)M_ROWS * D_MODEL];
__device__ __half g_WH[(size_t)4 * D_MODEL * D_MODEL];   // half(W[k][n])

__device__ __forceinline__ void mma_f16(float* c, const unsigned* a, const unsigned* b) {
    asm volatile(
        "mma.sync.aligned.m16n8k16.row.col.f32.f16.f16.f32 "
        "{%0,%1,%2,%3}, {%4,%5,%6,%7}, {%8,%9}, {%0,%1,%2,%3};\n"
        : "+f"(c[0]), "+f"(c[1]), "+f"(c[2]), "+f"(c[3])
        : "r"(a[0]), "r"(a[1]), "r"(a[2]), "r"(a[3]), "r"(b[0]), "r"(b[1]));
}

#define LDSM4(R0, R1, R2, R3, ADDR)                                           \
    asm volatile("ldmatrix.sync.aligned.m8n8.x4.shared.b16 {%0,%1,%2,%3}, [%4];" \
                 : "=r"(R0), "=r"(R1), "=r"(R2), "=r"(R3) : "r"(ADDR))
#define LDSM4T(R0, R1, R2, R3, ADDR)                                          \
    asm volatile("ldmatrix.sync.aligned.m8n8.x4.trans.shared.b16 {%0,%1,%2,%3}, [%4];" \
                 : "=r"(R0), "=r"(R1), "=r"(R2), "=r"(R3) : "r"(ADDR))

__device__ __forceinline__ uint32_t smem_u32(const void* p) {
    uint32_t a;
    asm("{ .reg .u64 t; cvta.to.shared.u64 t, %1; cvt.u32.u64 %0, t; }" : "=r"(a) : "l"(p));
    return a;
}

__device__ __forceinline__ void cp16(uint32_t dst, const void* src) {
    asm volatile("cp.async.cg.shared.global [%0], [%1], 16;" :: "r"(dst), "l"(src));
}
__device__ __forceinline__ void cp16z(uint32_t dst, const void* src, bool v) {
    int sz = v ? 16 : 0;
    asm volatile("cp.async.cg.shared.global [%0], [%1], 16, %2;"
                 :: "r"(dst), "l"(src), "r"(sz));
}

__device__ __forceinline__ unsigned h2u(__half2 h) {
    return *(unsigned*)&h;
}

// ---------------------------------------------------------------------------
// Weight-only fp16 prepass: WH[z][k][n] = half(W[k][n]). grid (1024, 4).
// ---------------------------------------------------------------------------
__global__ __launch_bounds__(256) void welem_h(
    const float* __restrict__ w0, const float* __restrict__ w1,
    const float* __restrict__ w2, const float* __restrict__ w3,
    __half* __restrict__ dst)
{
    const int z = blockIdx.y;
    const float* src = (z == 0) ? w0 : (z == 1) ? w1 : (z == 2) ? w2 : w3;
    __half* d = dst + (size_t)z * D_MODEL * D_MODEL;
    const size_t i4 = (size_t)blockIdx.x * 256 + threadIdx.x;
    float4 v = ((const float4*)src)[i4];
    *(__half2*)(d + i4 * 4)     = __floats2half2_rn(v.x, v.y);
    *(__half2*)(d + i4 * 4 + 2) = __floats2half2_rn(v.z, v.w);
}

// ---------------------------------------------------------------------------
// GEMM #1 (QKV): f32 A in (inline cvt during staging), half C out.
// Tile 128x128, BK=32, 3-stage cp.async (B) + register-prefetch (A).
// (R11/R16-proven kernel.)
// ---------------------------------------------------------------------------
#define GBM 128
#define GBN 128
#define G32_BK 32
#define G32_HSTR 40
#define G32_BHSTR 136
#define G32_A (GBM * G32_HSTR)        // 5120 halves
#define G32_B (G32_BK * G32_BHSTR)    // 4352 halves
#define G32_NS 3
#define G32_SMEM (G32_NS * (G32_A + G32_B) * 2)   // 56832 B

__global__ __launch_bounds__(256, 2) void hgemm_qkv(
    const float* __restrict__ A0, const float* __restrict__ A1, const float* __restrict__ A2,
    const __half* __restrict__ Wh,
    const float* __restrict__ b0, const float* __restrict__ b1, const float* __restrict__ b2,
    __half* __restrict__ C0, __half* __restrict__ C1, __half* __restrict__ C2)
{
    extern __shared__ __half shh[];
    const uint32_t sb = smem_u32(shh);

    const int z = blockIdx.z;
    const float* A    = (z == 0) ? A0 : (z == 1) ? A1 : A2;
    const __half* W   = Wh + (size_t)z * D_MODEL * D_MODEL;
    const float* bias = (z == 0) ? b0 : (z == 1) ? b1 : b2;
    __half* C         = (z == 0) ? C0 : (z == 1) ? C1 : C2;

    const int N = D_MODEL;
    const int tid  = threadIdx.x;
    const int bm   = blockIdx.y * GBM;
    const int bn   = blockIdx.x * GBN;
    const int warp = tid >> 5, lane = tid & 31;
    const int wm = warp & 1;
    const int wn = warp >> 1;
    const int g  = lane >> 2;
    const int tg = lane & 3;
    const int lj = lane >> 3, lr = lane & 7;

    const int am0 = tid >> 3, akq = tid & 7;
    const uint32_t a_base = (uint32_t)((wm * 64 + (lj & 1) * 8 + lr) * G32_HSTR + (lj >> 1) * 8);

    float acc[4][4][4];
#pragma unroll
    for (int mi = 0; mi < 4; mi++)
#pragma unroll
        for (int nj = 0; nj < 4; nj++)
#pragma unroll
            for (int r = 0; r < 4; r++) acc[mi][nj][r] = 0.f;

    auto stageB = [&](int p) {
        const int s = p % G32_NS;
        const uint32_t Bsb = sb + (uint32_t)(s * (G32_A + G32_B) + G32_A) * 2u;
        const int kp = p * G32_BK;
#pragma unroll
        for (int i = 0; i < 2; i++) {
            const int idx = tid + i * 256;
            const int row = idx >> 4, c = idx & 15;
            cp16(Bsb + (uint32_t)(row * (G32_BHSTR * 2) + c * 16),
                 W + (size_t)(kp + row) * N + bn + c * 8);
        }
        asm volatile("cp.async.commit_group;" ::: "memory");
    };
    auto ldA = [&](int p, float4* ar) {
        const int kp = p * G32_BK;
#pragma unroll
        for (int i = 0; i < 4; i++)
            ar[i] = *(const float4*)(A + (size_t)(bm + am0 + 32 * i) * D_MODEL + kp + akq * 4);
    };
    auto stA = [&](int p, const float4* ar) {
        const int s = p % G32_NS;
        __half* As = shh + s * (G32_A + G32_B);
#pragma unroll
        for (int i = 0; i < 4; i++) {
            *(__half2*)&As[(am0 + 32 * i) * G32_HSTR + akq * 4]     = __floats2half2_rn(ar[i].x, ar[i].y);
            *(__half2*)&As[(am0 + 32 * i) * G32_HSTR + akq * 4 + 2] = __floats2half2_rn(ar[i].z, ar[i].w);
        }
    };

    stageB(0);
    stageB(1);
    {
        float4 t[4];
        ldA(0, t); stA(0, t);
        ldA(1, t); stA(1, t);
    }

    const int NPAN = D_MODEL / G32_BK;   // 32
#pragma unroll 1
    for (int p = 0; p < NPAN; p++) {
        if (p < NPAN - 1)
            asm volatile("cp.async.wait_group 1;" ::: "memory");
        else
            asm volatile("cp.async.wait_group 0;" ::: "memory");
        __syncthreads();

        float4 ar[4];
        const bool pre = (p + 2 < NPAN);
        if (pre) {
            ldA(p + 2, ar);
            stageB(p + 2);
        }

        const int s = p % G32_NS;
        const uint32_t Ab32 = sb + (uint32_t)(s * (G32_A + G32_B)) * 2u;
        const uint32_t Bb32 = Ab32 + (uint32_t)G32_A * 2u;
#pragma unroll
        for (int ks = 0; ks < 2; ks++) {
            unsigned a[4][4], b[4][2];
#pragma unroll
            for (int mi = 0; mi < 4; mi++)
                LDSM4(a[mi][0], a[mi][1], a[mi][2], a[mi][3],
                      Ab32 + (a_base + mi * 16 * G32_HSTR + ks * 16) * 2u);
#pragma unroll
            for (int q = 0; q < 2; q++)
                LDSM4T(b[2 * q][0], b[2 * q][1], b[2 * q + 1][0], b[2 * q + 1][1],
                       Bb32 + ((uint32_t)((ks * 16 + (lj & 1) * 8 + lr) * G32_BHSTR)
                               + wn * 32 + (q * 2 + (lj >> 1)) * 8) * 2u);
#pragma unroll
            for (int mi = 0; mi < 4; mi++)
#pragma unroll
                for (int nj = 0; nj < 4; nj++)
                    mma_f16(acc[mi][nj], a[mi], b[nj]);
        }

        if (pre) stA(p + 2, ar);
    }

    // Epilogue: bias + store (half)
#pragma unroll
    for (int nj = 0; nj < 4; nj++) {
        const int col = bn + wn * 32 + nj * 8 + tg * 2;
        const float2 bv = *(const float2*)&bias[col];
#pragma unroll
        for (int mi = 0; mi < 4; mi++) {
            const int row0 = bm + wm * 64 + mi * 16 + g;
            *(__half2*)(C + (size_t)row0 * N + col) =
                __floats2half2_rn(acc[mi][nj][0] + bv.x, acc[mi][nj][1] + bv.y);
            *(__half2*)(C + (size_t)(row0 + 8) * N + col) =
                __floats2half2_rn(acc[mi][nj][2] + bv.x, acc[mi][nj][3] + bv.y);
        }
    }
}

// ---------------------------------------------------------------------------
// GEMM #2 (out-proj): half A in (pure cp.async), f32 C out.
// Tile 128x128, BK=64, 3-stage. (R14/R16-proven kernel, 35.4us.)
// ---------------------------------------------------------------------------
#define G64_BK 64
#define G64_HSTR 72
#define G64_BHSTR 136
#define G64_A (GBM * G64_HSTR)        // 9216 halves
#define G64_B (G64_BK * G64_BHSTR)    // 8704 halves
#define G64_NS 3
#define G64_SMEM (G64_NS * (G64_A + G64_B) * 2)   // 107520 B

__global__ __launch_bounds__(256, 2) void hgemm_out(
    const __half* __restrict__ A, const __half* __restrict__ W,
    const float* __restrict__ bias, float* __restrict__ C)
{
    extern __shared__ __half shh[];
    const uint32_t sb = smem_u32(shh);

    const int N = D_MODEL;
    const int tid  = threadIdx.x;
    const int bm   = blockIdx.y * GBM;
    const int bn   = blockIdx.x * GBN;
    const int warp = tid >> 5, lane = tid & 31;
    const int wm = warp & 1;
    const int wn = warp >> 1;
    const int g  = lane >> 2;
    const int tg = lane & 3;
    const int lj = lane >> 3, lr = lane & 7;

    const uint32_t a_base = (uint32_t)((wm * 64 + (lj & 1) * 8 + lr) * G64_HSTR + (lj >> 1) * 8);

    float acc[4][4][4];
#pragma unroll
    for (int mi = 0; mi < 4; mi++)
#pragma unroll
        for (int nj = 0; nj < 4; nj++)
#pragma unroll
            for (int r = 0; r < 4; r++) acc[mi][nj][r] = 0.f;

    auto stage = [&](int p) {
        const int s = p % G64_NS;
        const uint32_t Asb = sb + (uint32_t)(s * (G64_A + G64_B)) * 2u;
        const uint32_t Bsb = Asb + (uint32_t)G64_A * 2u;
        const int kp = p * G64_BK;
#pragma unroll
        for (int i = 0; i < 4; i++) {
            const int idx = tid + i * 256;
            const int row = idx >> 3, c = idx & 7;
            cp16(Asb + (uint32_t)(row * (G64_HSTR * 2) + c * 16),
                 A + (size_t)(bm + row) * D_MODEL + kp + c * 8);
        }
#pragma unroll
        for (int i = 0; i < 4; i++) {
            const int idx = tid + i * 256;
            const int row = idx >> 4, c = idx & 15;
            cp16(Bsb + (uint32_t)(row * (G64_BHSTR * 2) + c * 16),
                 W + (size_t)(kp + row) * N + bn + c * 8);
        }
        asm volatile("cp.async.commit_group;" ::: "memory");
    };

    stage(0);
    stage(1);

    const int NPAN = D_MODEL / G64_BK;   // 16
#pragma unroll 1
    for (int p = 0; p < NPAN; p++) {
        if (p < NPAN - 1)
            asm volatile("cp.async.wait_group 1;" ::: "memory");
        else
            asm volatile("cp.async.wait_group 0;" ::: "memory");
        __syncthreads();

        if (p + 2 < NPAN) stage(p + 2);

        const int s = p % G64_NS;
        const uint32_t Ab32 = sb + (uint32_t)(s * (G64_A + G64_B)) * 2u;
        const uint32_t Bb32 = Ab32 + (uint32_t)G64_A * 2u;
#pragma unroll
        for (int ks = 0; ks < 4; ks++) {
            unsigned a[4][4], b[4][2];
#pragma unroll
            for (int mi = 0; mi < 4; mi++)
                LDSM4(a[mi][0], a[mi][1], a[mi][2], a[mi][3],
                      Ab32 + (a_base + mi * 16 * G64_HSTR + ks * 16) * 2u);
#pragma unroll
            for (int q = 0; q < 2; q++)
                LDSM4T(b[2 * q][0], b[2 * q][1], b[2 * q + 1][0], b[2 * q + 1][1],
                       Bb32 + ((uint32_t)((ks * 16 + (lj & 1) * 8 + lr) * G64_BHSTR)
                               + wn * 32 + (q * 2 + (lj >> 1)) * 8) * 2u);
#pragma unroll
            for (int mi = 0; mi < 4; mi++)
#pragma unroll
                for (int nj = 0; nj < 4; nj++)
                    mma_f16(acc[mi][nj], a[mi], b[nj]);
        }
    }

    // Epilogue: bias + store (f32)
#pragma unroll
    for (int nj = 0; nj < 4; nj++) {
        const int col = bn + wn * 32 + nj * 8 + tg * 2;
        const float2 bv = *(const float2*)&bias[col];
#pragma unroll
        for (int mi = 0; mi < 4; mi++) {
            const int row0 = bm + wm * 64 + mi * 16 + g;
            float2 o0, o1;
            o0.x = acc[mi][nj][0] + bv.x;
            o0.y = acc[mi][nj][1] + bv.y;
            o1.x = acc[mi][nj][2] + bv.x;
            o1.y = acc[mi][nj][3] + bv.y;
            *(float2*)(C + (size_t)row0 * N + col)       = o0;
            *(float2*)(C + (size_t)(row0 + 8) * N + col) = o1;
        }
    }
}

// ---------------------------------------------------------------------------
// fp16 attention: chunk skip + REGISTER-RESIDENT P.
// Key identity: the C-fragment layout of S (c0,c1 = row g, cols 2tg/2tg+1;
// c2,c3 = row g+8) equals the A-fragment layout of P for the PV MMA:
//   pa0 = (e0,e1) of nt=2kt, pa1 = (e2,e3) of nt=2kt,
//   pa2 = (e0,e1) of nt=2kt+1, pa3 = (e2,e3) of nt=2kt+1.
// So exp results pack directly into A-fragments: no P SMEM, no syncwarp,
// no LDSM for P. Bit-identical output.
// ---------------------------------------------------------------------------
#define HKS 72
#define KS_OFF 0
#define VS_OFF (256 * HKS * 2)                  // 36864
#define BS_OFF (2 * VS_OFF)                     // 73728
#define ATTN_SMEM (BS_OFF + 132 * 4)            // 74256

__global__ __launch_bounds__(256, 2) void attn_h(
    const __half* __restrict__ Q, const __half* __restrict__ Kp,
    const __half* __restrict__ Vp, const float* __restrict__ rel,
    __half* __restrict__ O)
{
    extern __shared__ char smb[];
    float*  bsf = (float*)(smb + BS_OFF);
    const uint32_t sbase = smem_u32(smb);

    const int t0   = blockIdx.x * 128;
    const int h    = blockIdx.y;
    const int b    = blockIdx.z;
    const int base = t0 - WIN;
    const int tid  = threadIdx.x;
    const int warp = tid >> 5, lane = tid & 31;
    const int g = lane >> 2, tg = lane & 3;
    const int lj = lane >> 3, lr = lane & 7;

    const __half* Kg = Kp + (size_t)b * T_SEQ * D_MODEL + h * DK;
    const __half* Vg = Vp + (size_t)b * T_SEQ * D_MODEL + h * DK;

#pragma unroll
    for (int it = 0; it < 16; it++) {
        const int idx = tid + it * 256;
        const int sel = idx >> 11;
        const int r   = idx & 2047;
        const int key = r >> 3, d4 = r & 7;
        const int t   = base + key;
        const uint32_t dst = sbase + (sel ? VS_OFF : KS_OFF)
                           + (uint32_t)(key * HKS + d4 * 8) * 2u;
        const __half* src = (sel ? Vg : Kg) + (size_t)t * D_MODEL + d4 * 8;
        cp16z(dst, src, t >= 0 && t < T_SEQ);
    }
    asm volatile("cp.async.commit_group;" ::: "memory");
    if (tid < 2 * WIN + 1)
        bsf[tid] = rel[(size_t)(tid + MAXD - WIN) * H_HEADS + h];

    const int q0 = t0 + warp * 16;
    const __half* Qg = Q + (size_t)(b * T_SEQ + q0) * D_MODEL + h * DK;
    unsigned qa[4][4];
#pragma unroll
    for (int kt = 0; kt < 4; kt++) {
        const int k0 = kt * 16 + 2 * tg;
        qa[kt][0] = *(const unsigned*)(Qg + (size_t)g       * D_MODEL + k0);
        qa[kt][1] = *(const unsigned*)(Qg + (size_t)(g + 8) * D_MODEL + k0);
        qa[kt][2] = *(const unsigned*)(Qg + (size_t)g       * D_MODEL + k0 + 8);
        qa[kt][3] = *(const unsigned*)(Qg + (size_t)(g + 8) * D_MODEL + k0 + 8);
    }
    asm volatile("cp.async.wait_group 0;" ::: "memory");
    __syncthreads();

    float oacc[8][4];
#pragma unroll
    for (int nt = 0; nt < 8; nt++)
#pragma unroll
        for (int r = 0; r < 4; r++) oacc[nt][r] = 0.f;
    float rs0 = 0.f, rs1 = 0.f;

    const int cs = warp >> 2;   // w<4 -> chunks 0..2, w>=4 -> chunks 1..3
#pragma unroll 1
    for (int ci = 0; ci < 3; ci++) {
        const int c = cs + ci;
        // ---- S = Q @ K_chunk^T ----
        float sacc[8][4];
#pragma unroll
        for (int nt = 0; nt < 8; nt++)
#pragma unroll
            for (int r = 0; r < 4; r++) sacc[nt][r] = 0.f;
#pragma unroll
        for (int kt = 0; kt < 4; kt++) {
            unsigned kb[8][2];
#pragma unroll
            for (int q = 0; q < 4; q++) {
                const uint32_t row = (uint32_t)(c * 64 + (q * 2 + (lj >> 1)) * 8 + lr);
                LDSM4(kb[2 * q][0], kb[2 * q][1], kb[2 * q + 1][0], kb[2 * q + 1][1],
                      sbase + KS_OFF + (row * HKS + kt * 16 + (lj & 1) * 8) * 2u);
            }
#pragma unroll
            for (int nt = 0; nt < 8; nt++)
                mma_f16(sacc[nt], qa[kt], kb[nt]);
        }

        // ---- bias + band mask + exp -> P packed directly as A-fragments ----
        unsigned ep[8][2];
#pragma unroll
        for (int nt = 0; nt < 8; nt++) {
            const int col = c * 64 + nt * 8 + 2 * tg;
            const int tk  = base + col;
            const int d0  = tk - (q0 + g);
            const int d2  = tk - (q0 + 8 + g);
            float e0 = 0.f, e1 = 0.f, e2 = 0.f, e3 = 0.f;
            if (tk >= 0 && tk < T_SEQ) {
                if (d0 >= -WIN && d0 <= WIN) e0 = __expf(sacc[nt][0] * 0.125f + bsf[d0 + WIN]);
                if (d2 >= -WIN && d2 <= WIN) e2 = __expf(sacc[nt][2] * 0.125f + bsf[d2 + WIN]);
            }
            if (tk + 1 >= 0 && tk + 1 < T_SEQ) {
                if (d0 + 1 >= -WIN && d0 + 1 <= WIN) e1 = __expf(sacc[nt][1] * 0.125f + bsf[d0 + 1 + WIN]);
                if (d2 + 1 >= -WIN && d2 + 1 <= WIN) e3 = __expf(sacc[nt][3] * 0.125f + bsf[d2 + 1 + WIN]);
            }
            rs0 += e0 + e1;
            rs1 += e2 + e3;
            ep[nt][0] = h2u(__floats2half2_rn(e0, e1));   // row g   pair
            ep[nt][1] = h2u(__floats2half2_rn(e2, e3));   // row g+8 pair
        }

        // ---- O += P_chunk @ V_chunk (P from registers) ----
#pragma unroll
        for (int kt = 0; kt < 4; kt++) {
            unsigned pa[4];
            pa[0] = ep[2 * kt][0];
            pa[1] = ep[2 * kt][1];
            pa[2] = ep[2 * kt + 1][0];
            pa[3] = ep[2 * kt + 1][1];
            unsigned vb[8][2];
#pragma unroll
            for (int q = 0; q < 4; q++) {
                const uint32_t row = (uint32_t)(c * 64 + kt * 16 + (lj & 1) * 8 + lr);
                LDSM4T(vb[2 * q][0], vb[2 * q][1], vb[2 * q + 1][0], vb[2 * q + 1][1],
                       sbase + VS_OFF + (row * HKS + (q * 2 + (lj >> 1)) * 8) * 2u);
            }
#pragma unroll
            for (int nt = 0; nt < 8; nt++)
                mma_f16(oacc[nt], pa, vb[nt]);
        }
    }

    rs0 += __shfl_xor_sync(0xffffffffu, rs0, 1);
    rs0 += __shfl_xor_sync(0xffffffffu, rs0, 2);
    rs1 += __shfl_xor_sync(0xffffffffu, rs1, 1);
    rs1 += __shfl_xor_sync(0xffffffffu, rs1, 2);
    const float i0 = 1.f / rs0, i1 = 1.f / rs1;

    __half* Og = O + (size_t)(b * T_SEQ + q0) * D_MODEL + h * DK;
#pragma unroll
    for (int nt = 0; nt < 8; nt++) {
        *(__half2*)(Og + (size_t)g       * D_MODEL + nt * 8 + 2 * tg) =
            __floats2half2_rn(oacc[nt][0] * i0, oacc[nt][1] * i0);
        *(__half2*)(Og + (size_t)(g + 8) * D_MODEL + nt * 8 + 2 * tg) =
            __floats2half2_rn(oacc[nt][2] * i1, oacc[nt][3] * i1);
    }
}

// ---------------------------------------------------------------------------
// Launch
// ---------------------------------------------------------------------------
extern "C" void kernel_launch(void* const* d_in, const int* in_sizes, int n_in,
                              void* d_out, int out_size)
{
    const float* q_in = (const float*)d_in[0];
    const float* k_in = (const float*)d_in[1];
    const float* v_in = (const float*)d_in[2];
    const float* Wq   = (const float*)d_in[3];
    const float* bq   = (const float*)d_in[4];
    const float* Wk   = (const float*)d_in[5];
    const float* bk   = (const float*)d_in[6];
    const float* Wv   = (const float*)d_in[7];
    const float* bv   = (const float*)d_in[8];
    const float* Wo   = (const float*)d_in[9];
    const float* bo   = (const float*)d_in[10];
    const float* rel  = (const float*)d_in[11];
    float* out = (float*)d_out;

    __half *pQ, *pK, *pV, *pA, *pWH;
    cudaGetSymbolAddress((void**)&pQ, g_Qh);
    cudaGetSymbolAddress((void**)&pK, g_Kh);
    cudaGetSymbolAddress((void**)&pV, g_Vh);
    cudaGetSymbolAddress((void**)&pA, g_Ah);
    cudaGetSymbolAddress((void**)&pWH, g_WH);

    cudaFuncSetAttribute(hgemm_qkv, cudaFuncAttributeMaxDynamicSharedMemorySize,
                         (int)G32_SMEM);
    cudaFuncSetAttribute(hgemm_out, cudaFuncAttributeMaxDynamicSharedMemorySize,
                         (int)G64_SMEM);
    cudaFuncSetAttribute(attn_h, cudaFuncAttributeMaxDynamicSharedMemorySize,
                         (int)ATTN_SMEM);

    const size_t WSZ = (size_t)D_MODEL * D_MODEL;

    // Weight-only fp16 prepass (~4us).
    welem_h<<<dim3(D_MODEL * D_MODEL / 4 / 256, 4), 256>>>(Wq, Wk, Wv, Wo, pWH);

    // Fused Q/K/V projections: f32 in (inline cvt), half out.
    dim3 g3(D_MODEL / GBN, M_ROWS / GBM, 3);
    hgemm_qkv<<<g3, 256, G32_SMEM>>>(q_in, k_in, v_in, pWH,
                                     bq, bk, bv, pQ, pK, pV);

    attn_h<<<dim3(T_SEQ / 128, H_HEADS, B_SZ), 256, ATTN_SMEM>>>(pQ, pK, pV, rel, pA);

    // Output projection: half in, f32 out, BK=64.
    dim3 g1(D_MODEL / GBN, M_ROWS / GBM, 1);
    hgemm_out<<<g1, 256, G64_SMEM>>>(pA, pWH + 3 * WSZ, bo, out);
}